// round 6
// baseline (speedup 1.0000x reference)
#include <cuda_runtime.h>
#include <cuda_bf16.h>

// U1_circuit v5: packed f32x2 state (qubit-0 spectator lanes), layer-0 RX
// folded into product-state init, CX subtractions via sub.rn.f32x2 (rt-2 on
// the RF banks vs rt-3 for 3-operand ffma2). Natural register allocation
// (no forced occupancy -> no spills; v4 post-mortem).
//
// inputs: (32,32,32,3) f32   kernel: (8,1,15) f32   out: (32,31,31,8) f32

#define NB 32
#define NH 32
#define NW 32
#define NC 3
#define NY 31
#define NX 31
#define NF 8

#define PIX_PER_BLK 16
#define THREADS 128

typedef unsigned long long u64;

__device__ __forceinline__ u64 pk(float lo, float hi) {
    u64 r; asm("mov.b64 %0, {%1, %2};" : "=l"(r) : "f"(lo), "f"(hi)); return r;
}
__device__ __forceinline__ void unpk(float& lo, float& hi, u64 v) {
    asm("mov.b64 {%0, %1}, %2;" : "=f"(lo), "=f"(hi) : "l"(v));
}
__device__ __forceinline__ u64 bc2(float x) { return pk(x, x); }
__device__ __forceinline__ u64 ffma2(u64 a, u64 b, u64 c) {
    u64 d; asm("fma.rn.f32x2 %0, %1, %2, %3;" : "=l"(d) : "l"(a), "l"(b), "l"(c)); return d;
}
__device__ __forceinline__ u64 fmul2(u64 a, u64 b) {
    u64 d; asm("mul.rn.f32x2 %0, %1, %2;" : "=l"(d) : "l"(a), "l"(b)); return d;
}
__device__ __forceinline__ u64 fadd2(u64 a, u64 b) {
    u64 d; asm("add.rn.f32x2 %0, %1, %2;" : "=l"(d) : "l"(a), "l"(b)); return d;
}
__device__ __forceinline__ u64 fsub2(u64 a, u64 b) {
    u64 d; asm("sub.rn.f32x2 %0, %1, %2;" : "=l"(d) : "l"(a), "l"(b)); return d;
}

__global__ void __launch_bounds__(THREADS)
qsim_kernel(const float* __restrict__ inp,
            const float* __restrict__ ker,
            float* __restrict__ out)
{
    __shared__ float2 s_rx[PIX_PER_BLK][12];  // (sn, cs) per pixel, gate j*4+i
    __shared__ float2 s_cx[NF][12];           // (br, bi) per filter, gate j*4+g
    __shared__ float2 s_cz[NF][3];            // (lr, li) per filter, layer j

    const int tid  = threadIdx.x;
    const int pix0 = blockIdx.x * PIX_PER_BLK;

    // ---- cooperative precompute: RX angles (16 pixels x 12 gates) ----
#pragma unroll
    for (int k = tid; k < PIX_PER_BLK * 12; k += THREADS) {
        const int pl  = k / 12;
        const int g   = k - pl * 12;
        const int pix = pix0 + pl;
        const int x   = pix % NX;
        const int y   = (pix / NX) % NY;
        const int b   = pix / (NX * NY);
        const int i   = g & 3;
        const int j   = g >> 2;
        const int yy  = y + (i >> 1);
        const int xx  = x + (i & 1);
        const float a = inp[((size_t)(b * NH + yy) * NW + xx) * NC + j];
        float sn, cs;
        sincospif(0.5f * a, &sn, &cs);
        s_rx[pl][g] = make_float2(sn, cs);
    }

    // ---- cooperative precompute: filter params (8 filters x 15) ----
    if (tid < NF * 15) {
        const int f = tid / 15;
        const int q = tid - f * 15;
        const float p = ker[f * 15 + q];
        float li, lr;
        sincospif(p, &li, &lr);              // lambda = exp(i*pi*p)
        const int j  = q / 5;
        const int q5 = q - j * 5;
        if (q5 < 4) {
            s_cx[f][j * 4 + q5] = make_float2(0.5f * (1.f - lr), -0.5f * li);
        } else {
            s_cz[f][j] = make_float2(lr, li);
        }
    }
    __syncthreads();

    const int pl = tid >> 3;
    const int f  = tid & (NF - 1);

    // ---- initial state = H|0> (q0) x RX|0> (q1..4): product construction ----
    // amp[m] = (-i)^popc(m) * prod(c_i or s_i); lanes identical (q0 untouched).
    u64 R[16], I[16];
    {
        const float2 g0 = s_rx[pl][0];   // qubit1 (bit 8)
        const float2 g1 = s_rx[pl][1];   // qubit2 (bit 4)
        const float2 g2 = s_rx[pl][2];   // qubit3 (bit 2)
        const float2 g3 = s_rx[pl][3];   // qubit4 (bit 1)
        const float IS2 = 0.70710678118654752440f;
        float A[4], B[4];
        A[0] = g0.y * g1.y * IS2;  A[1] = g0.y * g1.x * IS2;
        A[2] = g0.x * g1.y * IS2;  A[3] = g0.x * g1.x * IS2;
        B[0] = g2.y * g3.y;        B[1] = g2.y * g3.x;
        B[2] = g2.x * g3.y;        B[3] = g2.x * g3.x;
#pragma unroll
        for (int m = 0; m < 16; m++) {
            const float p = A[m >> 2] * B[m & 3];
            const int k = __popc(m) & 3;     // compile-time per unrolled m
            const float rv = (k == 0) ? p : ((k == 2) ? -p : 0.f);
            const float iv = (k == 1) ? -p : ((k == 3) ? p : 0.f);
            R[m] = pk(rv, rv);
            I[m] = pk(iv, iv);
        }
    }

#pragma unroll
    for (int j = 0; j < 3; j++) {
        // ---- RX gates (layer 0 folded into init) ----
        if (j > 0) {
#pragma unroll
            for (int i = 0; i < 4; i++) {
                const float2 sc = s_rx[pl][j * 4 + i];
                const u64 sn2  = bc2(sc.x);
                const u64 nsn2 = bc2(-sc.x);
                const u64 cs2  = bc2(sc.y);
                const int bit = 8 >> i;
#pragma unroll
                for (int m = 0; m < 16; m++) {
                    if (m & bit) continue;
                    const int m1 = m | bit;
                    const u64 r0 = R[m],  i0 = I[m];
                    const u64 r1 = R[m1], i1 = I[m1];
                    R[m]  = ffma2(cs2, r0, fmul2(sn2,  i1));
                    I[m]  = ffma2(cs2, i0, fmul2(nsn2, r1));
                    R[m1] = ffma2(cs2, r1, fmul2(sn2,  i0));
                    I[m1] = ffma2(cs2, i1, fmul2(nsn2, r0));
                }
            }
        }

        // ---- CX^p: e = b*(y-x); x += e; y -= e  (subs via sub.rn.f32x2) ----
        const int bcb[4] = {8, 4, 2, 1};
        const int btb[4] = {4, 2, 1, 8};
#pragma unroll
        for (int g = 0; g < 4; g++) {
            const float2 bb = s_cx[f][j * 4 + g];
            const u64 br2  = bc2(bb.x);
            const u64 bi2  = bc2(bb.y);
            const u64 nbi2 = bc2(-bb.y);
            const int Bc = bcb[g], Bt = btb[g];
#pragma unroll
            for (int m = 0; m < 16; m++) {
                if (!(m & Bc) || (m & Bt)) continue;   // control=1, target=0
                const int m1 = m | Bt;
                const u64 dR = fsub2(R[m1], R[m]);
                const u64 dI = fsub2(I[m1], I[m]);
                const u64 eR = ffma2(br2, dR, fmul2(nbi2, dI));
                const u64 eI = ffma2(br2, dI, fmul2(bi2,  dR));
                R[m]  = fadd2(R[m],  eR);
                I[m]  = fadd2(I[m],  eI);
                R[m1] = fsub2(R[m1], eR);
                I[m1] = fsub2(I[m1], eI);
            }
        }

        // ---- CZ^p on (1,0): bit8 set (m>=8), bit16 -> hi lane only ----
        {
            const float2 ll = s_cz[f][j];
            const u64 Lr  = pk(1.0f,  ll.x);
            const u64 Li  = pk(0.0f,  ll.y);
            const u64 nLi = pk(0.0f, -ll.y);
#pragma unroll
            for (int m = 8; m < 16; m++) {
                const u64 xr = R[m], xi = I[m];
                R[m] = ffma2(Lr, xr, fmul2(nLi, xi));
                I[m] = ffma2(Lr, xi, fmul2(Li,  xr));
            }
        }
    }

    // ---- exp = 2 * sum_m (sr[m]*sr[m+16] + si[m]*si[m+16]) ----
    float e = 0.f;
#pragma unroll
    for (int m = 0; m < 16; m++) {
        float rl, rh, il, ih;
        unpk(rl, rh, R[m]);
        unpk(il, ih, I[m]);
        e += rl * rh + il * ih;
    }
    e *= 2.f;
    e = fminf(fmaxf(e, -1.f + 1e-5f), 1.f - 1e-5f);
    out[blockIdx.x * THREADS + tid] = acosf(e) * 0.31830988618379067154f;
}

extern "C" void kernel_launch(void* const* d_in, const int* in_sizes, int n_in,
                              void* d_out, int out_size)
{
    const float* inp = (const float*)d_in[0];
    const float* ker = (const float*)d_in[1];
    float* out = (float*)d_out;
    const int total = NB * NY * NX * NF;        // 246016
    const int blocks = total / THREADS;         // 1922 exactly
    qsim_kernel<<<blocks, THREADS>>>(inp, ker, out);
}

// round 7
// speedup vs baseline: 1.0992x; 1.0992x over previous
#include <cuda_runtime.h>
#include <cuda_bf16.h>

// U1_circuit v6: packed f32x2 state; layer-0 RX folded into product init;
// layer-0 CX run scalar (lanes identical until first CZ -> scalar FFMA rt2
// instead of packed rt3); CZ1 scalar on hi halves via free b64 aliasing;
// CZ2 folded into readout; 64-thread blocks for finer tail granularity.
//
// inputs: (32,32,32,3) f32   kernel: (8,1,15) f32   out: (32,31,31,8) f32

#define NB 32
#define NH 32
#define NW 32
#define NC 3
#define NY 31
#define NX 31
#define NF 8

#define PIX_PER_BLK 8
#define THREADS 64

typedef unsigned long long u64;

__device__ __forceinline__ u64 pk(float lo, float hi) {
    u64 r; asm("mov.b64 %0, {%1, %2};" : "=l"(r) : "f"(lo), "f"(hi)); return r;
}
__device__ __forceinline__ void unpk(float& lo, float& hi, u64 v) {
    asm("mov.b64 {%0, %1}, %2;" : "=f"(lo), "=f"(hi) : "l"(v));
}
__device__ __forceinline__ u64 bc2(float x) { return pk(x, x); }
__device__ __forceinline__ u64 ffma2(u64 a, u64 b, u64 c) {
    u64 d; asm("fma.rn.f32x2 %0, %1, %2, %3;" : "=l"(d) : "l"(a), "l"(b), "l"(c)); return d;
}
__device__ __forceinline__ u64 fmul2(u64 a, u64 b) {
    u64 d; asm("mul.rn.f32x2 %0, %1, %2;" : "=l"(d) : "l"(a), "l"(b)); return d;
}
__device__ __forceinline__ u64 fadd2(u64 a, u64 b) {
    u64 d; asm("add.rn.f32x2 %0, %1, %2;" : "=l"(d) : "l"(a), "l"(b)); return d;
}
__device__ __forceinline__ u64 fsub2(u64 a, u64 b) {
    u64 d; asm("sub.rn.f32x2 %0, %1, %2;" : "=l"(d) : "l"(a), "l"(b)); return d;
}

__global__ void __launch_bounds__(THREADS)
qsim_kernel(const float* __restrict__ inp,
            const float* __restrict__ ker,
            float* __restrict__ out)
{
    __shared__ float2 s_rx[PIX_PER_BLK][12];  // (sn, cs) per pixel, gate j*4+i
    __shared__ float2 s_cx[NF][12];           // (br, bi) per filter, gate j*4+g
    __shared__ float2 s_cz[NF][3];            // (lr, li) per filter, layer j

    const int tid  = threadIdx.x;
    const int pix0 = blockIdx.x * PIX_PER_BLK;

    // ---- cooperative precompute: RX angles (8 pixels x 12 gates) ----
#pragma unroll
    for (int k = tid; k < PIX_PER_BLK * 12; k += THREADS) {
        const int pl  = k / 12;
        const int g   = k - pl * 12;
        const int pix = pix0 + pl;
        const int x   = pix % NX;
        const int y   = (pix / NX) % NY;
        const int b   = pix / (NX * NY);
        const int i   = g & 3;
        const int j   = g >> 2;
        const int yy  = y + (i >> 1);
        const int xx  = x + (i & 1);
        const float a = inp[((size_t)(b * NH + yy) * NW + xx) * NC + j];
        float sn, cs;
        sincospif(0.5f * a, &sn, &cs);
        s_rx[pl][g] = make_float2(sn, cs);
    }

    // ---- cooperative precompute: filter params (8 filters x 15) ----
    for (int k = tid; k < NF * 15; k += THREADS) {
        const int f = k / 15;
        const int q = k - f * 15;
        const float p = ker[f * 15 + q];
        float li, lr;
        sincospif(p, &li, &lr);              // lambda = exp(i*pi*p)
        const int j  = q / 5;
        const int q5 = q - j * 5;
        if (q5 < 4) {
            s_cx[f][j * 4 + q5] = make_float2(0.5f * (1.f - lr), -0.5f * li);
        } else {
            s_cz[f][j] = make_float2(lr, li);
        }
    }
    __syncthreads();

    const int pl = tid >> 3;
    const int f  = tid & (NF - 1);

    const int bcb[4] = {8, 4, 2, 1};
    const int btb[4] = {4, 2, 1, 8};

    // ================= scalar phase: lanes identical until first CZ ========
    // initial state = H|0>(q0) x RX|0>(q1..4): amp[m] = (-i)^popc(m) * prod
    float ar[16], ai[16];
    {
        const float2 g0 = s_rx[pl][0];   // qubit1 (bit 8)
        const float2 g1 = s_rx[pl][1];   // qubit2 (bit 4)
        const float2 g2 = s_rx[pl][2];   // qubit3 (bit 2)
        const float2 g3 = s_rx[pl][3];   // qubit4 (bit 1)
        const float IS2 = 0.70710678118654752440f;
        float A[4], B[4];
        A[0] = g0.y * g1.y * IS2;  A[1] = g0.y * g1.x * IS2;
        A[2] = g0.x * g1.y * IS2;  A[3] = g0.x * g1.x * IS2;
        B[0] = g2.y * g3.y;        B[1] = g2.y * g3.x;
        B[2] = g2.x * g3.y;        B[3] = g2.x * g3.x;
#pragma unroll
        for (int m = 0; m < 16; m++) {
            const float p = A[m >> 2] * B[m & 3];
            const int k = __popc(m) & 3;
            ar[m] = (k == 0) ? p : ((k == 2) ? -p : 0.f);
            ai[m] = (k == 1) ? -p : ((k == 3) ? p : 0.f);
        }
    }

    // layer-0 CX gates, scalar
#pragma unroll
    for (int g = 0; g < 4; g++) {
        const float2 bb = s_cx[f][g];
        const float br = bb.x, bi = bb.y;
        const int Bc = bcb[g], Bt = btb[g];
#pragma unroll
        for (int m = 0; m < 16; m++) {
            if (!(m & Bc) || (m & Bt)) continue;
            const int m1 = m | Bt;
            const float dr = ar[m1] - ar[m];
            const float di = ai[m1] - ai[m];
            const float er = br * dr - bi * di;
            const float ei = br * di + bi * dr;
            ar[m]  += er;  ai[m]  += ei;
            ar[m1] -= er;  ai[m1] -= ei;
        }
    }

    // layer-0 CZ while packing: hi lane of m>=8 gets *lambda0
    u64 R[16], I[16];
    {
        const float2 ll = s_cz[f][0];
        const float lr = ll.x, li = ll.y;
#pragma unroll
        for (int m = 0; m < 8; m++) {
            R[m] = pk(ar[m], ar[m]);
            I[m] = pk(ai[m], ai[m]);
        }
#pragma unroll
        for (int m = 8; m < 16; m++) {
            const float hr = lr * ar[m] - li * ai[m];
            const float hi = lr * ai[m] + li * ar[m];
            R[m] = pk(ar[m], hr);
            I[m] = pk(ai[m], hi);
        }
    }

    // ================= packed phase: layers 1 and 2 ========================
#pragma unroll
    for (int j = 1; j < 3; j++) {
        // ---- RX on qubits 1..4 (bits 8,4,2,1) ----
#pragma unroll
        for (int i = 0; i < 4; i++) {
            const float2 sc = s_rx[pl][j * 4 + i];
            const u64 sn2  = bc2(sc.x);
            const u64 nsn2 = bc2(-sc.x);
            const u64 cs2  = bc2(sc.y);
            const int bit = 8 >> i;
#pragma unroll
            for (int m = 0; m < 16; m++) {
                if (m & bit) continue;
                const int m1 = m | bit;
                const u64 r0 = R[m],  i0 = I[m];
                const u64 r1 = R[m1], i1 = I[m1];
                R[m]  = ffma2(cs2, r0, fmul2(sn2,  i1));
                I[m]  = ffma2(cs2, i0, fmul2(nsn2, r1));
                R[m1] = ffma2(cs2, r1, fmul2(sn2,  i0));
                I[m1] = ffma2(cs2, i1, fmul2(nsn2, r0));
            }
        }

        // ---- CX^p: e = b*(y-x); x += e; y -= e ----
#pragma unroll
        for (int g = 0; g < 4; g++) {
            const float2 bb = s_cx[f][j * 4 + g];
            const u64 br2  = bc2(bb.x);
            const u64 bi2  = bc2(bb.y);
            const u64 nbi2 = bc2(-bb.y);
            const int Bc = bcb[g], Bt = btb[g];
#pragma unroll
            for (int m = 0; m < 16; m++) {
                if (!(m & Bc) || (m & Bt)) continue;
                const int m1 = m | Bt;
                const u64 dR = fsub2(R[m1], R[m]);
                const u64 dI = fsub2(I[m1], I[m]);
                const u64 eR = ffma2(br2, dR, fmul2(nbi2, dI));
                const u64 eI = ffma2(br2, dI, fmul2(bi2,  dR));
                R[m]  = fadd2(R[m],  eR);
                I[m]  = fadd2(I[m],  eI);
                R[m1] = fsub2(R[m1], eR);
                I[m1] = fsub2(I[m1], eI);
            }
        }

        // ---- CZ: layer 1 scalar on hi halves; layer 2 folded into readout --
        if (j == 1) {
            const float2 ll = s_cz[f][1];
            const float lr = ll.x, li = ll.y;
#pragma unroll
            for (int m = 8; m < 16; m++) {
                float lo_r, hi_r, lo_i, hi_i;
                unpk(lo_r, hi_r, R[m]);
                unpk(lo_i, hi_i, I[m]);
                const float nhr = lr * hi_r - li * hi_i;
                const float nhi = lr * hi_i + li * hi_r;
                R[m] = pk(lo_r, nhr);
                I[m] = pk(lo_i, nhi);
            }
        }
    }

    // ---- readout with CZ2 folded in:
    // e = 2*[ sum_{m<8} Re(conj(lo) hi) + Re(lambda2 * sum_{m>=8} conj(lo) hi) ]
    float e = 0.f;
#pragma unroll
    for (int m = 0; m < 8; m++) {
        float rl, rh, il, ih;
        unpk(rl, rh, R[m]);
        unpk(il, ih, I[m]);
        e += rl * rh + il * ih;
    }
    float cr = 0.f, ci = 0.f;
#pragma unroll
    for (int m = 8; m < 16; m++) {
        float rl, rh, il, ih;
        unpk(rl, rh, R[m]);
        unpk(il, ih, I[m]);
        cr += rl * rh + il * ih;     // Re(conj(lo)*hi)
        ci += rl * ih - il * rh;     // Im(conj(lo)*hi)
    }
    {
        const float2 ll = s_cz[f][2];
        e += ll.x * cr - ll.y * ci;
    }
    e *= 2.f;
    e = fminf(fmaxf(e, -1.f + 1e-5f), 1.f - 1e-5f);
    out[blockIdx.x * THREADS + tid] = acosf(e) * 0.31830988618379067154f;
}

extern "C" void kernel_launch(void* const* d_in, const int* in_sizes, int n_in,
                              void* d_out, int out_size)
{
    const float* inp = (const float*)d_in[0];
    const float* ker = (const float*)d_in[1];
    float* out = (float*)d_out;
    const int total = NB * NY * NX * NF;        // 246016
    const int blocks = total / THREADS;         // 3844 exactly
    qsim_kernel<<<blocks, THREADS>>>(inp, ker, out);
}